// round 1
// baseline (speedup 1.0000x reference)
#include <cuda_runtime.h>
#include <cuda_bf16.h>

// Problem constants (fixed by the dataset)
#define Bn 4
#define Nn 50000
#define Dn 256
#define En 800000
#define NPTS (Bn * Nn)   // 200000

// Double-buffered XPBD state, float4 (w unused) so gathers are single LDG.128
// and scatter-adds are single red.global.add.v4.f32. 2 x 3.2 MB static.
__device__ float4 g_x[2][NPTS];

__device__ __forceinline__ void red_add_v4(float4* p, float a, float b, float c) {
    asm volatile("red.global.add.v4.f32 [%0], {%1, %2, %3, %4};"
                 :: "l"(p), "f"(a), "f"(b), "f"(c), "f"(0.0f)
                 : "memory");
}

// ---------------------------------------------------------------------------
// Stage 1: x_pred = keypoints + tau * (hand_tokens @ head_w + head_b)
// One warp per point. Lane i loads float4 at cols 4i and 128+4i (two fully
// coalesced 512B warp transactions), FMAs against smem weights, shfl-reduce.
// ---------------------------------------------------------------------------
__global__ __launch_bounds__(256) void predict_kernel(
    const float* __restrict__ kp, const float* __restrict__ ts,
    const float* __restrict__ ht, const float* __restrict__ hw,
    const float* __restrict__ hb)
{
    __shared__ float sw[Dn * 3];
    __shared__ float sb[3];
    int tid = threadIdx.x;
    for (int i = tid; i < Dn * 3; i += blockDim.x) sw[i] = hw[i];
    if (tid < 3) sb[tid] = hb[tid];
    __syncthreads();

    int warp = tid >> 5, lane = tid & 31;
    int p = blockIdx.x * 8 + warp;   // 8 warps per block, 1 point per warp
    if (p >= NPTS) return;

    const float4* h = reinterpret_cast<const float4*>(ht + (size_t)p * Dn);
    float4 h0 = __ldg(&h[lane]);        // cols [4*lane .. 4*lane+3]
    float4 h1 = __ldg(&h[32 + lane]);   // cols [128+4*lane ..]

    float a0 = 0.f, a1 = 0.f, a2 = 0.f;
    float hv[8] = {h0.x, h0.y, h0.z, h0.w, h1.x, h1.y, h1.z, h1.w};
    int   c0 = 4 * lane, c1 = 128 + 4 * lane;
    int   cc[8] = {c0, c0 + 1, c0 + 2, c0 + 3, c1, c1 + 1, c1 + 2, c1 + 3};
#pragma unroll
    for (int i = 0; i < 8; i++) {
        a0 = fmaf(hv[i], sw[cc[i] * 3 + 0], a0);
        a1 = fmaf(hv[i], sw[cc[i] * 3 + 1], a1);
        a2 = fmaf(hv[i], sw[cc[i] * 3 + 2], a2);
    }
#pragma unroll
    for (int o = 16; o >= 1; o >>= 1) {
        a0 += __shfl_xor_sync(0xffffffffu, a0, o);
        a1 += __shfl_xor_sync(0xffffffffu, a1, o);
        a2 += __shfl_xor_sync(0xffffffffu, a2, o);
    }
    if (lane == 0) {
        int b = p / Nn;
        float tau = fmaxf(1.0f - __ldg(&ts[b]), 0.001f);
        float kx = __ldg(&kp[(size_t)p * 3 + 0]);
        float ky = __ldg(&kp[(size_t)p * 3 + 1]);
        float kz = __ldg(&kp[(size_t)p * 3 + 2]);
        float4 o;
        o.x = fmaf(tau, a0 + sb[0], kx);
        o.y = fmaf(tau, a1 + sb[1], ky);
        o.z = fmaf(tau, a2 + sb[2], kz);
        o.w = 0.0f;
        g_x[0][p] = o;
    }
}

// ---------------------------------------------------------------------------
// Copy x -> x_next (Jacobi base for the RED accumulation). 3.2 MB, trivial.
// ---------------------------------------------------------------------------
__global__ __launch_bounds__(256) void copy_kernel(int from, int to)
{
    int i = blockIdx.x * blockDim.x + threadIdx.x;
    if (i < NPTS) g_x[to][i] = g_x[from][i];
}

// ---------------------------------------------------------------------------
// One XPBD Jacobi iteration. Thread per edge, inner loop over 4 batches
// (amortizes the edge_index / rest_length loads 4x). Gathers hit L2 (state is
// 3.2 MB). Scatter = vectorized L2 RED, one per endpoint.
// ---------------------------------------------------------------------------
__global__ __launch_bounds__(256) void edge_kernel(
    const int* __restrict__ ei, const float* __restrict__ rest,
    int from, int to)
{
    int e = blockIdx.x * blockDim.x + threadIdx.x;
    if (e >= En) return;
    int   s  = __ldg(&ei[e]);
    int   d  = __ldg(&ei[En + e]);
    float L0 = __ldg(&rest[e]);

    const float4* xin  = g_x[from];
    float4*       xout = g_x[to];

#pragma unroll
    for (int b = 0; b < Bn; b++) {
        float4 xs = __ldg(&xin[b * Nn + s]);
        float4 xd = __ldg(&xin[b * Nn + d]);
        float dx = xs.x - xd.x;
        float dy = xs.y - xd.y;
        float dz = xs.z - xd.z;
        float dist = sqrtf(dx * dx + dy * dy + dz * dz);
        // correction = clip( (-(dist-L0)/denom) * diff/(dist+1e-9), +-0.15 )
        // denom = w_i + w_j + alpha + 1e-9 = 2 (alpha = 0, 1e-9 below fp32 ulp)
        float scale = (L0 - dist) * 0.5f / (dist + 1e-9f);
        float cx = fminf(fmaxf(scale * dx, -0.15f), 0.15f);
        float cy = fminf(fmaxf(scale * dy, -0.15f), 0.15f);
        float cz = fminf(fmaxf(scale * dz, -0.15f), 0.15f);
        red_add_v4(&xout[b * Nn + s],  cx,  cy,  cz);
        red_add_v4(&xout[b * Nn + d], -cx, -cy, -cz);
    }
}

// ---------------------------------------------------------------------------
// Stage 3: v_eff = (x_corrected - keypoints) / tau
// ---------------------------------------------------------------------------
__global__ __launch_bounds__(256) void final_kernel(
    const float* __restrict__ kp, const float* __restrict__ ts,
    int buf, float* __restrict__ out)
{
    int p = blockIdx.x * blockDim.x + threadIdx.x;
    if (p >= NPTS) return;
    int b = p / Nn;
    float tau = fmaxf(1.0f - __ldg(&ts[b]), 0.001f);
    float4 x = g_x[buf][p];
    out[(size_t)p * 3 + 0] = (x.x - __ldg(&kp[(size_t)p * 3 + 0])) / tau;
    out[(size_t)p * 3 + 1] = (x.y - __ldg(&kp[(size_t)p * 3 + 1])) / tau;
    out[(size_t)p * 3 + 2] = (x.z - __ldg(&kp[(size_t)p * 3 + 2])) / tau;
}

extern "C" void kernel_launch(void* const* d_in, const int* in_sizes, int n_in,
                              void* d_out, int out_size)
{
    const float* kp   = (const float*)d_in[0];  // keypoints   (B,N,3)
    const float* ts   = (const float*)d_in[1];  // timesteps   (B,)
    const float* ht   = (const float*)d_in[2];  // hand_tokens (B,N,D)
    const float* hw   = (const float*)d_in[3];  // head_w      (D,3)
    const float* hb   = (const float*)d_in[4];  // head_b      (3,)
    const int*   ei   = (const int*)  d_in[5];  // edge_index  (2,E)
    const float* rest = (const float*)d_in[6];  // rest_lengths(E,)
    float*       out  = (float*)d_out;          // v_eff       (B,N,3)

    (void)in_sizes; (void)n_in; (void)out_size;

    // Stage 1: prediction into g_x[0]
    predict_kernel<<<NPTS / 8, 256>>>(kp, ts, ht, hw, hb);

    // Stage 2: 4 Jacobi XPBD iterations, ping-pong buffers
    int cur = 0;
    const int copy_blocks = (NPTS + 255) / 256;
    const int edge_blocks = (En + 255) / 256;
#pragma unroll
    for (int it = 0; it < 4; it++) {
        int nxt = cur ^ 1;
        copy_kernel<<<copy_blocks, 256>>>(cur, nxt);
        edge_kernel<<<edge_blocks, 256>>>(ei, rest, cur, nxt);
        cur = nxt;
    }

    // Stage 3: velocity output (cur == 0 after 4 iterations)
    final_kernel<<<copy_blocks, 256>>>(kp, ts, cur, out);
}

// round 2
// speedup vs baseline: 1.2771x; 1.2771x over previous
#include <cuda_runtime.h>
#include <cuda_bf16.h>

// Problem constants (fixed by the dataset)
#define Bn 4
#define Nn 50000
#define Dn 256
#define En 800000
#define NPTS (Bn * Nn)   // 200000

// XPBD state, node-major packed: node n owns 12 floats (4 batches x xyz):
//   [12n+0..2]=b0, [12n+3..5]=b1, [12n+6..8]=b2, [12n+9..11]=b3
// = 3 float4s per node -> gathers are 3 consecutive LDG.128 (2 L2 sectors),
// scatter-adds are 3 red.global.add.v4.f32. Two ping-pong buffers, 2.4MB each.
__device__ float g_xf[2][NPTS * 12];

__device__ __forceinline__ void red_add_v4(float4* p, float a, float b,
                                           float c, float d) {
    asm volatile("red.global.add.v4.f32 [%0], {%1, %2, %3, %4};"
                 :: "l"(p), "f"(a), "f"(b), "f"(c), "f"(d)
                 : "memory");
}

// ---------------------------------------------------------------------------
// Stage 1: x_pred = keypoints + tau * (hand_tokens @ head_w + head_b)
// One warp per point (b,n). Lane i loads float4 at cols 4i and 128+4i (two
// fully coalesced 512B warp transactions), FMAs against smem weights,
// shfl-reduce. Writes the packed node-major state into BOTH buffers so the
// first XPBD iteration needs no copy.
// ---------------------------------------------------------------------------
__global__ __launch_bounds__(256) void predict_kernel(
    const float* __restrict__ kp, const float* __restrict__ ts,
    const float* __restrict__ ht, const float* __restrict__ hw,
    const float* __restrict__ hb)
{
    __shared__ float sw[Dn * 3];
    __shared__ float sb[3];
    int tid = threadIdx.x;
    for (int i = tid; i < Dn * 3; i += blockDim.x) sw[i] = hw[i];
    if (tid < 3) sb[tid] = hb[tid];
    __syncthreads();

    int warp = tid >> 5, lane = tid & 31;
    int p = blockIdx.x * 8 + warp;   // 8 warps per block, 1 point per warp
    if (p >= NPTS) return;

    const float4* h = reinterpret_cast<const float4*>(ht + (size_t)p * Dn);
    float4 h0 = __ldg(&h[lane]);        // cols [4*lane .. 4*lane+3]
    float4 h1 = __ldg(&h[32 + lane]);   // cols [128+4*lane ..]

    float a0 = 0.f, a1 = 0.f, a2 = 0.f;
    float hv[8] = {h0.x, h0.y, h0.z, h0.w, h1.x, h1.y, h1.z, h1.w};
    int   c0 = 4 * lane, c1 = 128 + 4 * lane;
    int   cc[8] = {c0, c0 + 1, c0 + 2, c0 + 3, c1, c1 + 1, c1 + 2, c1 + 3};
#pragma unroll
    for (int i = 0; i < 8; i++) {
        a0 = fmaf(hv[i], sw[cc[i] * 3 + 0], a0);
        a1 = fmaf(hv[i], sw[cc[i] * 3 + 1], a1);
        a2 = fmaf(hv[i], sw[cc[i] * 3 + 2], a2);
    }
#pragma unroll
    for (int o = 16; o >= 1; o >>= 1) {
        a0 += __shfl_xor_sync(0xffffffffu, a0, o);
        a1 += __shfl_xor_sync(0xffffffffu, a1, o);
        a2 += __shfl_xor_sync(0xffffffffu, a2, o);
    }
    if (lane == 0) {
        int b = p / Nn;
        int n = p - b * Nn;
        float tau = fmaxf(1.0f - __ldg(&ts[b]), 0.001f);
        float kx = __ldg(&kp[(size_t)p * 3 + 0]);
        float ky = __ldg(&kp[(size_t)p * 3 + 1]);
        float kz = __ldg(&kp[(size_t)p * 3 + 2]);
        float vx = fmaf(tau, a0 + sb[0], kx);
        float vy = fmaf(tau, a1 + sb[1], ky);
        float vz = fmaf(tau, a2 + sb[2], kz);
        int base = 12 * n + 3 * b;
        g_xf[0][base + 0] = vx;  g_xf[1][base + 0] = vx;
        g_xf[0][base + 1] = vy;  g_xf[1][base + 1] = vy;
        g_xf[0][base + 2] = vz;  g_xf[1][base + 2] = vz;
    }
}

// ---------------------------------------------------------------------------
// Copy x -> x_next (Jacobi base for the RED accumulation). 2.4 MB as float4.
// ---------------------------------------------------------------------------
__global__ __launch_bounds__(256) void copy_kernel(int from, int to)
{
    int i = blockIdx.x * blockDim.x + threadIdx.x;
    if (i < NPTS * 3)
        reinterpret_cast<float4*>(g_xf[to])[i] =
            reinterpret_cast<const float4*>(g_xf[from])[i];
}

// ---------------------------------------------------------------------------
// One XPBD Jacobi iteration. Thread per edge, all 4 batches per thread.
// Node-major 48B packing: per thread 6 LDG.128 gather (4 sectors total) +
// 6 RED.v4 scatter (4 sectors). All L2-resident.
// ---------------------------------------------------------------------------
__global__ __launch_bounds__(256) void edge_kernel(
    const int* __restrict__ ei, const float* __restrict__ rest,
    int from, int to)
{
    int e = blockIdx.x * blockDim.x + threadIdx.x;
    if (e >= En) return;
    int   s  = __ldg(&ei[e]);
    int   d  = __ldg(&ei[En + e]);
    float L0 = __ldg(&rest[e]);

    const float4* xin  = reinterpret_cast<const float4*>(g_xf[from]);
    float4*       xout = reinterpret_cast<float4*>(g_xf[to]);

    float4 s0 = __ldg(&xin[3 * s + 0]);
    float4 s1 = __ldg(&xin[3 * s + 1]);
    float4 s2 = __ldg(&xin[3 * s + 2]);
    float4 d0 = __ldg(&xin[3 * d + 0]);
    float4 d1 = __ldg(&xin[3 * d + 1]);
    float4 d2 = __ldg(&xin[3 * d + 2]);

    float sx[4] = {s0.x, s0.w, s1.z, s2.y};
    float sy[4] = {s0.y, s1.x, s1.w, s2.z};
    float sz[4] = {s0.z, s1.y, s2.x, s2.w};
    float tx[4] = {d0.x, d0.w, d1.z, d2.y};
    float ty[4] = {d0.y, d1.x, d1.w, d2.z};
    float tz[4] = {d0.z, d1.y, d2.x, d2.w};

    float cx[4], cy[4], cz[4];
#pragma unroll
    for (int b = 0; b < Bn; b++) {
        float dx = sx[b] - tx[b];
        float dy = sy[b] - ty[b];
        float dz = sz[b] - tz[b];
        float dist = sqrtf(dx * dx + dy * dy + dz * dz);
        // correction = clip( (-(dist-L0)/denom) * diff/(dist+1e-9), +-0.15 )
        // denom = w_i + w_j + alpha + 1e-9 = 2
        float scale = (L0 - dist) * 0.5f / (dist + 1e-9f);
        cx[b] = fminf(fmaxf(scale * dx, -0.15f), 0.15f);
        cy[b] = fminf(fmaxf(scale * dy, -0.15f), 0.15f);
        cz[b] = fminf(fmaxf(scale * dz, -0.15f), 0.15f);
    }

    red_add_v4(&xout[3 * s + 0],  cx[0],  cy[0],  cz[0],  cx[1]);
    red_add_v4(&xout[3 * s + 1],  cy[1],  cz[1],  cx[2],  cy[2]);
    red_add_v4(&xout[3 * s + 2],  cz[2],  cx[3],  cy[3],  cz[3]);
    red_add_v4(&xout[3 * d + 0], -cx[0], -cy[0], -cz[0], -cx[1]);
    red_add_v4(&xout[3 * d + 1], -cy[1], -cz[1], -cx[2], -cy[2]);
    red_add_v4(&xout[3 * d + 2], -cz[2], -cx[3], -cy[3], -cz[3]);
}

// ---------------------------------------------------------------------------
// Stage 3: v_eff = (x_corrected - keypoints) / tau
// Thread per node: 48B fully-coalesced state read, per-batch coalesced writes.
// ---------------------------------------------------------------------------
__global__ __launch_bounds__(256) void final_kernel(
    const float* __restrict__ kp, const float* __restrict__ ts,
    int buf, float* __restrict__ out)
{
    int n = blockIdx.x * blockDim.x + threadIdx.x;
    if (n >= Nn) return;
    const float4* x = reinterpret_cast<const float4*>(g_xf[buf]);
    float4 q0 = x[3 * n + 0];
    float4 q1 = x[3 * n + 1];
    float4 q2 = x[3 * n + 2];
    float px[4] = {q0.x, q0.w, q1.z, q2.y};
    float py[4] = {q0.y, q1.x, q1.w, q2.z};
    float pz[4] = {q0.z, q1.y, q2.x, q2.w};
#pragma unroll
    for (int b = 0; b < Bn; b++) {
        float inv_tau = 1.0f / fmaxf(1.0f - __ldg(&ts[b]), 0.001f);
        size_t o = (size_t)(b * Nn + n) * 3;
        out[o + 0] = (px[b] - __ldg(&kp[o + 0])) * inv_tau;
        out[o + 1] = (py[b] - __ldg(&kp[o + 1])) * inv_tau;
        out[o + 2] = (pz[b] - __ldg(&kp[o + 2])) * inv_tau;
    }
}

extern "C" void kernel_launch(void* const* d_in, const int* in_sizes, int n_in,
                              void* d_out, int out_size)
{
    const float* kp   = (const float*)d_in[0];  // keypoints   (B,N,3)
    const float* ts   = (const float*)d_in[1];  // timesteps   (B,)
    const float* ht   = (const float*)d_in[2];  // hand_tokens (B,N,D)
    const float* hw   = (const float*)d_in[3];  // head_w      (D,3)
    const float* hb   = (const float*)d_in[4];  // head_b      (3,)
    const int*   ei   = (const int*)  d_in[5];  // edge_index  (2,E)
    const float* rest = (const float*)d_in[6];  // rest_lengths(E,)
    float*       out  = (float*)d_out;          // v_eff       (B,N,3)

    (void)in_sizes; (void)n_in; (void)out_size;

    const int copy_blocks  = (NPTS * 3 + 255) / 256;
    const int edge_blocks  = (En + 255) / 256;
    const int final_blocks = (Nn + 255) / 256;

    // Stage 1: prediction into BOTH buffers (first iteration needs no copy)
    predict_kernel<<<NPTS / 8, 256>>>(kp, ts, ht, hw, hb);

    // Stage 2: 4 Jacobi XPBD iterations, ping-pong buffers
    // iter0: 0 -> 1 (buffers identical after predict)
    edge_kernel<<<edge_blocks, 256>>>(ei, rest, 0, 1);
    // iter1: 1 -> 0
    copy_kernel<<<copy_blocks, 256>>>(1, 0);
    edge_kernel<<<edge_blocks, 256>>>(ei, rest, 1, 0);
    // iter2: 0 -> 1
    copy_kernel<<<copy_blocks, 256>>>(0, 1);
    edge_kernel<<<edge_blocks, 256>>>(ei, rest, 0, 1);
    // iter3: 1 -> 0
    copy_kernel<<<copy_blocks, 256>>>(1, 0);
    edge_kernel<<<edge_blocks, 256>>>(ei, rest, 1, 0);

    // Stage 3: velocity output from buffer 0
    final_kernel<<<final_blocks, 256>>>(kp, ts, 0, out);
}